// round 1
// baseline (speedup 1.0000x reference)
#include <cuda_runtime.h>
#include <math.h>

#define BB 2
#define SS 128
#define DD 128
#define FF 512
#define VV 1024
#define HH 4
#define DK 32
#define LL 2
#define MROWS (BB*SS)   // 256

// ---------------- scratch (device globals; no allocation allowed) ----------------
__device__ float g_x[MROWS*DD];
__device__ float g_lin[MROWS*DD];
__device__ float g_q[MROWS*DD];
__device__ float g_k[MROWS*DD];
__device__ float g_v[MROWS*DD];
__device__ float g_att[MROWS*DD];
__device__ float g_ff[MROWS*FF];
// transformed weights, stored TRANSPOSED per layer: tw[k*N + n] = f(W[n*K + k])
__device__ float g_twq[LL*DD*DD];
__device__ float g_twk[LL*DD*DD];
__device__ float g_twv[LL*DD*DD];
__device__ float g_two[LL*DD*DD];
__device__ float g_tw1[LL*FF*DD];
__device__ float g_tw2[LL*DD*FF];
__device__ float g_twout[VV*DD];

// ---------------- l_mul elementwise transform ----------------
// Reference: e = (|x|>0) ? floor(log2|x|)+1 : 0 ;  m = x*2^-e ; r = round(m*8)
// l_mul term = rx*ry*2^(2(ex+ey)-6) = f(x)*f(w),  f(x) = r * 2^(2e-3).
// We use log2f (same formula as the jax reference) so the e-convention near
// powers of two matches the reference's own rounding, not frexp's.
__device__ __forceinline__ float lmul_f(float x) {
    float ax = fabsf(x);
    if (ax == 0.0f) return 0.0f;
    int e = (int)floorf(log2f(ax)) + 1;
    float m = ldexpf(x, -e);          // exact scaling
    float r = rintf(m * 8.0f);        // round-half-even, matches jnp.round
    return ldexpf(r, 2*e - 3);        // exact scaling
}

// ---------------- weight transform + transpose ----------------
// src: (N,K) row-major. dst: (K,N) so GEMM reads are coalesced over n.
__global__ void transform_w(const float* __restrict__ src, float* __restrict__ dst,
                            int N, int K) {
    int idx = blockIdx.x * blockDim.x + threadIdx.x;
    if (idx < N * K) {
        int n = idx / K, k = idx - n * K;
        dst[k * N + n] = lmul_f(src[idx]);
    }
}

// ---------------- embedding + positional ----------------
__global__ void embed_kernel(const int* __restrict__ tokens,
                             const float* __restrict__ emb,
                             const float* __restrict__ pos,
                             float* __restrict__ x) {
    int row = blockIdx.x;            // b*S + s
    int s = row % SS;
    int d = threadIdx.x;             // 128 = D
    int tok = tokens[row];
    x[row * DD + d] = emb[tok * DD + d] + pos[s * DD + d];
}

// ---------------- generic linear: Y = f(X) @ twT + bias (optional relu) ----------
// twT is (K,N). One block per row of X; threads stride over N.
__global__ void linear_f(const float* __restrict__ X,
                         const float* __restrict__ twT,
                         const float* __restrict__ bias,
                         float* __restrict__ Y,
                         int K, int N, int relu) {
    int row = blockIdx.x;
    extern __shared__ float xt[];    // K floats
    for (int k = threadIdx.x; k < K; k += blockDim.x)
        xt[k] = lmul_f(X[row * K + k]);
    __syncthreads();
    for (int n = threadIdx.x; n < N; n += blockDim.x) {
        float acc = bias[n];
        #pragma unroll 8
        for (int k = 0; k < K; ++k)
            acc = fmaf(xt[k], twT[k * N + n], acc);
        if (relu) acc = fmaxf(acc, 0.0f);
        Y[row * N + n] = acc;
    }
}

// ---------------- attention: one block per (b,h), one thread per query ----------
__global__ void attn_kernel(const float* __restrict__ q,
                            const float* __restrict__ k,
                            const float* __restrict__ v,
                            float* __restrict__ out) {
    int b = blockIdx.x / HH;
    int h = blockIdx.x % HH;
    __shared__ float ksh[SS * DK];
    __shared__ float vsh[SS * DK];
    int tid = threadIdx.x;           // 128 threads = S queries
    for (int i = tid; i < SS * DK; i += blockDim.x) {
        int j = i / DK, d = i - j * DK;
        ksh[i] = k[(b * SS + j) * DD + h * DK + d];
        vsh[i] = v[(b * SS + j) * DD + h * DK + d];
    }
    __syncthreads();

    float qr[DK];
    #pragma unroll
    for (int d = 0; d < DK; ++d) qr[d] = q[(b * SS + tid) * DD + h * DK + d];

    const float scale = 1.0f / sqrtf((float)DK);

    // pass 1: max
    float mmax = -INFINITY;
    for (int j = 0; j < SS; ++j) {
        float s = 0.0f;
        #pragma unroll
        for (int d = 0; d < DK; ++d) s = fmaf(qr[d], ksh[j * DK + d], s);
        mmax = fmaxf(mmax, s * scale);
    }
    // pass 2: exp-sum + weighted V accumulation
    float l = 0.0f;
    float o[DK];
    #pragma unroll
    for (int d = 0; d < DK; ++d) o[d] = 0.0f;
    for (int j = 0; j < SS; ++j) {
        float s = 0.0f;
        #pragma unroll
        for (int d = 0; d < DK; ++d) s = fmaf(qr[d], ksh[j * DK + d], s);
        float p = expf(s * scale - mmax);
        l += p;
        #pragma unroll
        for (int d = 0; d < DK; ++d) o[d] = fmaf(p, vsh[j * DK + d], o[d]);
    }
    float inv = 1.0f / l;
    #pragma unroll
    for (int d = 0; d < DK; ++d)
        out[(b * SS + tid) * DD + h * DK + d] = o[d] * inv;
}

// ---------------- residual add + layernorm (in place into x) ----------------
__global__ void add_ln_kernel(float* __restrict__ x,
                              const float* __restrict__ a,
                              const float* __restrict__ g,
                              const float* __restrict__ be) {
    int row = blockIdx.x;
    int tid = threadIdx.x;           // 128 = D
    __shared__ float sh[4];

    float val = x[row * DD + tid] + a[row * DD + tid];

    // mean
    float s = val;
    #pragma unroll
    for (int o = 16; o > 0; o >>= 1) s += __shfl_xor_sync(0xffffffffu, s, o);
    if ((tid & 31) == 0) sh[tid >> 5] = s;
    __syncthreads();
    float mean = (sh[0] + sh[1] + sh[2] + sh[3]) * (1.0f / DD);
    __syncthreads();

    float c = val - mean;
    float s2 = c * c;
    #pragma unroll
    for (int o = 16; o > 0; o >>= 1) s2 += __shfl_xor_sync(0xffffffffu, s2, o);
    if ((tid & 31) == 0) sh[tid >> 5] = s2;
    __syncthreads();
    float var = (sh[0] + sh[1] + sh[2] + sh[3]) * (1.0f / DD);

    float y = c * (1.0f / sqrtf(var + 1e-5f)) * g[tid] + be[tid];
    x[row * DD + tid] = y;
}

// ---------------- host-side orchestration ----------------
static float* sym(const void* symbol) {
    void* p = nullptr;
    cudaGetSymbolAddress(&p, symbol);
    return (float*)p;
}

extern "C" void kernel_launch(void* const* d_in, const int* in_sizes, int n_in,
                              void* d_out, int out_size) {
    const int*   tokens = (const int*)  d_in[0];
    const float* emb    = (const float*)d_in[1];
    const float* pos    = (const float*)d_in[2];
    const float* Wq     = (const float*)d_in[3];
    const float* bq     = (const float*)d_in[4];
    const float* Wk     = (const float*)d_in[5];
    const float* bk     = (const float*)d_in[6];
    const float* Wv     = (const float*)d_in[7];
    const float* bv     = (const float*)d_in[8];
    const float* Wo     = (const float*)d_in[9];
    const float* bo     = (const float*)d_in[10];
    const float* W1     = (const float*)d_in[11];
    const float* b1     = (const float*)d_in[12];
    const float* W2     = (const float*)d_in[13];
    const float* b2     = (const float*)d_in[14];
    const float* g1     = (const float*)d_in[15];
    const float* be1    = (const float*)d_in[16];
    const float* g2     = (const float*)d_in[17];
    const float* be2    = (const float*)d_in[18];
    const float* Wout   = (const float*)d_in[19];
    const float* bout   = (const float*)d_in[20];
    float* out = (float*)d_out;

    float* x_   = sym(g_x);
    float* lin_ = sym(g_lin);
    float* q_   = sym(g_q);
    float* k_   = sym(g_k);
    float* v_   = sym(g_v);
    float* att_ = sym(g_att);
    float* ff_  = sym(g_ff);
    float* twq_ = sym(g_twq);
    float* twk_ = sym(g_twk);
    float* twv_ = sym(g_twv);
    float* two_ = sym(g_two);
    float* tw1_ = sym(g_tw1);
    float* tw2_ = sym(g_tw2);
    float* twout_ = sym(g_twout);

    // ---- transform all weights (every call; deterministic) ----
    const int TB = 256;
    for (int l = 0; l < LL; ++l) {
        int offDD = l * DD * DD;
        transform_w<<<(DD*DD + TB-1)/TB, TB>>>(Wq + offDD, twq_ + offDD, DD, DD);
        transform_w<<<(DD*DD + TB-1)/TB, TB>>>(Wk + offDD, twk_ + offDD, DD, DD);
        transform_w<<<(DD*DD + TB-1)/TB, TB>>>(Wv + offDD, twv_ + offDD, DD, DD);
        transform_w<<<(DD*DD + TB-1)/TB, TB>>>(Wo + offDD, two_ + offDD, DD, DD);
        transform_w<<<(FF*DD + TB-1)/TB, TB>>>(W1 + l*FF*DD, tw1_ + l*FF*DD, FF, DD);
        transform_w<<<(DD*FF + TB-1)/TB, TB>>>(W2 + l*DD*FF, tw2_ + l*DD*FF, DD, FF);
    }
    transform_w<<<(VV*DD + TB-1)/TB, TB>>>(Wout, twout_, VV, DD);

    // ---- embedding + positional ----
    embed_kernel<<<MROWS, DD>>>(tokens, emb, pos, x_);

    // ---- layers ----
    for (int l = 0; l < LL; ++l) {
        int offDD = l * DD * DD;
        linear_f<<<MROWS, 128, DD*sizeof(float)>>>(x_, twq_ + offDD, bq + l*DD, q_, DD, DD, 0);
        linear_f<<<MROWS, 128, DD*sizeof(float)>>>(x_, twk_ + offDD, bk + l*DD, k_, DD, DD, 0);
        linear_f<<<MROWS, 128, DD*sizeof(float)>>>(x_, twv_ + offDD, bv + l*DD, v_, DD, DD, 0);

        attn_kernel<<<BB*HH, SS>>>(q_, k_, v_, att_);

        linear_f<<<MROWS, 128, DD*sizeof(float)>>>(att_, two_ + offDD, bo + l*DD, lin_, DD, DD, 0);
        add_ln_kernel<<<MROWS, DD>>>(x_, lin_, g1 + l*DD, be1 + l*DD);

        linear_f<<<MROWS, 256, DD*sizeof(float)>>>(x_, tw1_ + l*FF*DD, b1 + l*FF, ff_, DD, FF, 1);
        linear_f<<<MROWS, 128, FF*sizeof(float)>>>(ff_, tw2_ + l*DD*FF, b2 + l*DD, lin_, FF, DD, 0);
        add_ln_kernel<<<MROWS, DD>>>(x_, lin_, g2 + l*DD, be2 + l*DD);
    }

    // ---- final projection into d_out ----
    linear_f<<<MROWS, 256, DD*sizeof(float)>>>(x_, twout_, bout, out, DD, VV, 0);
}

// round 2
// speedup vs baseline: 1.0062x; 1.0062x over previous
#include <cuda_runtime.h>
#include <math.h>

#define BB 2
#define SS 128
#define DD 128
#define FF 512
#define VV 1024
#define HH 4
#define DK 32
#define LL 2
#define MROWS (BB*SS)   // 256

// ---------------- scratch (device globals; no allocation allowed) ----------------
__device__ float g_x[MROWS*DD];
__device__ float g_lin[MROWS*DD];
__device__ float g_q[MROWS*DD];
__device__ float g_k[MROWS*DD];
__device__ float g_v[MROWS*DD];
__device__ float g_att[MROWS*DD];
__device__ float g_ff[MROWS*FF];
// transformed weights, stored TRANSPOSED per layer: tw[k*N + n] = f(W[n*K + k])
__device__ float g_twq[LL*DD*DD];
__device__ float g_twk[LL*DD*DD];
__device__ float g_twv[LL*DD*DD];
__device__ float g_two[LL*DD*DD];
__device__ float g_tw1[LL*FF*DD];
__device__ float g_tw2[LL*DD*FF];
__device__ float g_twout[VV*DD];

// ---------------- l_mul elementwise transform ----------------
// Reference: e = (|x|>0) ? floor(log2|x|)+1 : 0 ;  m = x*2^-e ; r = round(m*8)
// l_mul term = rx*ry*2^(2(ex+ey)-6) = f(x)*f(w),  f(x) = r * 2^(2e-3).
// We use log2f (same formula as the jax reference) so the e-convention near
// powers of two matches the reference's own rounding, not frexp's.
__device__ __forceinline__ float lmul_f(float x) {
    float ax = fabsf(x);
    if (ax == 0.0f) return 0.0f;
    int e = (int)floorf(log2f(ax)) + 1;
    float m = ldexpf(x, -e);          // exact scaling
    float r = rintf(m * 8.0f);        // round-half-even, matches jnp.round
    return ldexpf(r, 2*e - 3);        // exact scaling
}

// ---------------- weight transform + transpose ----------------
// src: (N,K) row-major. dst: (K,N) so GEMM reads are coalesced over n.
__global__ void transform_w(const float* __restrict__ src, float* __restrict__ dst,
                            int N, int K) {
    int idx = blockIdx.x * blockDim.x + threadIdx.x;
    if (idx < N * K) {
        int n = idx / K, k = idx - n * K;
        dst[k * N + n] = lmul_f(src[idx]);
    }
}

// ---------------- embedding + positional ----------------
__global__ void embed_kernel(const int* __restrict__ tokens,
                             const float* __restrict__ emb,
                             const float* __restrict__ pos,
                             float* __restrict__ x) {
    int row = blockIdx.x;            // b*S + s
    int s = row % SS;
    int d = threadIdx.x;             // 128 = D
    int tok = tokens[row];
    x[row * DD + d] = emb[tok * DD + d] + pos[s * DD + d];
}

// ---------------- generic linear: Y = f(X) @ twT + bias (optional relu) ----------
// twT is (K,N). One block per row of X; threads stride over N.
__global__ void linear_f(const float* __restrict__ X,
                         const float* __restrict__ twT,
                         const float* __restrict__ bias,
                         float* __restrict__ Y,
                         int K, int N, int relu) {
    int row = blockIdx.x;
    extern __shared__ float xt[];    // K floats
    for (int k = threadIdx.x; k < K; k += blockDim.x)
        xt[k] = lmul_f(X[row * K + k]);
    __syncthreads();
    for (int n = threadIdx.x; n < N; n += blockDim.x) {
        float acc = bias[n];
        #pragma unroll 8
        for (int k = 0; k < K; ++k)
            acc = fmaf(xt[k], twT[k * N + n], acc);
        if (relu) acc = fmaxf(acc, 0.0f);
        Y[row * N + n] = acc;
    }
}

// ---------------- attention: one block per (b,h), one thread per query ----------
__global__ void attn_kernel(const float* __restrict__ q,
                            const float* __restrict__ k,
                            const float* __restrict__ v,
                            float* __restrict__ out) {
    int b = blockIdx.x / HH;
    int h = blockIdx.x % HH;
    __shared__ float ksh[SS * DK];
    __shared__ float vsh[SS * DK];
    int tid = threadIdx.x;           // 128 threads = S queries
    for (int i = tid; i < SS * DK; i += blockDim.x) {
        int j = i / DK, d = i - j * DK;
        ksh[i] = k[(b * SS + j) * DD + h * DK + d];
        vsh[i] = v[(b * SS + j) * DD + h * DK + d];
    }
    __syncthreads();

    float qr[DK];
    #pragma unroll
    for (int d = 0; d < DK; ++d) qr[d] = q[(b * SS + tid) * DD + h * DK + d];

    const float scale = 1.0f / sqrtf((float)DK);

    // pass 1: max
    float mmax = -INFINITY;
    for (int j = 0; j < SS; ++j) {
        float s = 0.0f;
        #pragma unroll
        for (int d = 0; d < DK; ++d) s = fmaf(qr[d], ksh[j * DK + d], s);
        mmax = fmaxf(mmax, s * scale);
    }
    // pass 2: exp-sum + weighted V accumulation
    float l = 0.0f;
    float o[DK];
    #pragma unroll
    for (int d = 0; d < DK; ++d) o[d] = 0.0f;
    for (int j = 0; j < SS; ++j) {
        float s = 0.0f;
        #pragma unroll
        for (int d = 0; d < DK; ++d) s = fmaf(qr[d], ksh[j * DK + d], s);
        float p = expf(s * scale - mmax);
        l += p;
        #pragma unroll
        for (int d = 0; d < DK; ++d) o[d] = fmaf(p, vsh[j * DK + d], o[d]);
    }
    float inv = 1.0f / l;
    #pragma unroll
    for (int d = 0; d < DK; ++d)
        out[(b * SS + tid) * DD + h * DK + d] = o[d] * inv;
}

// ---------------- residual add + layernorm (in place into x) ----------------
__global__ void add_ln_kernel(float* __restrict__ x,
                              const float* __restrict__ a,
                              const float* __restrict__ g,
                              const float* __restrict__ be) {
    int row = blockIdx.x;
    int tid = threadIdx.x;           // 128 = D
    __shared__ float sh[4];

    float val = x[row * DD + tid] + a[row * DD + tid];

    // mean
    float s = val;
    #pragma unroll
    for (int o = 16; o > 0; o >>= 1) s += __shfl_xor_sync(0xffffffffu, s, o);
    if ((tid & 31) == 0) sh[tid >> 5] = s;
    __syncthreads();
    float mean = (sh[0] + sh[1] + sh[2] + sh[3]) * (1.0f / DD);
    __syncthreads();

    float c = val - mean;
    float s2 = c * c;
    #pragma unroll
    for (int o = 16; o > 0; o >>= 1) s2 += __shfl_xor_sync(0xffffffffu, s2, o);
    if ((tid & 31) == 0) sh[tid >> 5] = s2;
    __syncthreads();
    float var = (sh[0] + sh[1] + sh[2] + sh[3]) * (1.0f / DD);

    float y = c * (1.0f / sqrtf(var + 1e-5f)) * g[tid] + be[tid];
    x[row * DD + tid] = y;
}

// ---------------- host-side orchestration ----------------
static float* sym(const void* symbol) {
    void* p = nullptr;
    cudaGetSymbolAddress(&p, symbol);
    return (float*)p;
}

extern "C" void kernel_launch(void* const* d_in, const int* in_sizes, int n_in,
                              void* d_out, int out_size) {
    const int*   tokens = (const int*)  d_in[0];
    const float* emb    = (const float*)d_in[1];
    const float* pos    = (const float*)d_in[2];
    const float* Wq     = (const float*)d_in[3];
    const float* bq     = (const float*)d_in[4];
    const float* Wk     = (const float*)d_in[5];
    const float* bk     = (const float*)d_in[6];
    const float* Wv     = (const float*)d_in[7];
    const float* bv     = (const float*)d_in[8];
    const float* Wo     = (const float*)d_in[9];
    const float* bo     = (const float*)d_in[10];
    const float* W1     = (const float*)d_in[11];
    const float* b1     = (const float*)d_in[12];
    const float* W2     = (const float*)d_in[13];
    const float* b2     = (const float*)d_in[14];
    const float* g1     = (const float*)d_in[15];
    const float* be1    = (const float*)d_in[16];
    const float* g2     = (const float*)d_in[17];
    const float* be2    = (const float*)d_in[18];
    const float* Wout   = (const float*)d_in[19];
    const float* bout   = (const float*)d_in[20];
    float* out = (float*)d_out;

    float* x_   = sym(g_x);
    float* lin_ = sym(g_lin);
    float* q_   = sym(g_q);
    float* k_   = sym(g_k);
    float* v_   = sym(g_v);
    float* att_ = sym(g_att);
    float* ff_  = sym(g_ff);
    float* twq_ = sym(g_twq);
    float* twk_ = sym(g_twk);
    float* twv_ = sym(g_twv);
    float* two_ = sym(g_two);
    float* tw1_ = sym(g_tw1);
    float* tw2_ = sym(g_tw2);
    float* twout_ = sym(g_twout);

    // ---- transform all weights (every call; deterministic) ----
    const int TB = 256;
    for (int l = 0; l < LL; ++l) {
        int offDD = l * DD * DD;
        transform_w<<<(DD*DD + TB-1)/TB, TB>>>(Wq + offDD, twq_ + offDD, DD, DD);
        transform_w<<<(DD*DD + TB-1)/TB, TB>>>(Wk + offDD, twk_ + offDD, DD, DD);
        transform_w<<<(DD*DD + TB-1)/TB, TB>>>(Wv + offDD, twv_ + offDD, DD, DD);
        transform_w<<<(DD*DD + TB-1)/TB, TB>>>(Wo + offDD, two_ + offDD, DD, DD);
        transform_w<<<(FF*DD + TB-1)/TB, TB>>>(W1 + l*FF*DD, tw1_ + l*FF*DD, FF, DD);
        transform_w<<<(DD*FF + TB-1)/TB, TB>>>(W2 + l*DD*FF, tw2_ + l*DD*FF, DD, FF);
    }
    transform_w<<<(VV*DD + TB-1)/TB, TB>>>(Wout, twout_, VV, DD);

    // ---- embedding + positional ----
    embed_kernel<<<MROWS, DD>>>(tokens, emb, pos, x_);

    // ---- layers ----
    for (int l = 0; l < LL; ++l) {
        int offDD = l * DD * DD;
        linear_f<<<MROWS, 128, DD*sizeof(float)>>>(x_, twq_ + offDD, bq + l*DD, q_, DD, DD, 0);
        linear_f<<<MROWS, 128, DD*sizeof(float)>>>(x_, twk_ + offDD, bk + l*DD, k_, DD, DD, 0);
        linear_f<<<MROWS, 128, DD*sizeof(float)>>>(x_, twv_ + offDD, bv + l*DD, v_, DD, DD, 0);

        attn_kernel<<<BB*HH, SS>>>(q_, k_, v_, att_);

        linear_f<<<MROWS, 128, DD*sizeof(float)>>>(att_, two_ + offDD, bo + l*DD, lin_, DD, DD, 0);
        add_ln_kernel<<<MROWS, DD>>>(x_, lin_, g1 + l*DD, be1 + l*DD);

        linear_f<<<MROWS, 256, DD*sizeof(float)>>>(x_, tw1_ + l*FF*DD, b1 + l*FF, ff_, DD, FF, 1);
        linear_f<<<MROWS, 128, FF*sizeof(float)>>>(ff_, tw2_ + l*DD*FF, b2 + l*DD, lin_, FF, DD, 0);
        add_ln_kernel<<<MROWS, DD>>>(x_, lin_, g2 + l*DD, be2 + l*DD);
    }

    // ---- final projection into d_out ----
    linear_f<<<MROWS, 256, DD*sizeof(float)>>>(x_, twout_, bout, out, DD, VV, 0);
}

// round 3
// speedup vs baseline: 3.0318x; 3.0133x over previous
#include <cuda_runtime.h>
#include <math.h>

#define NB 128
#define NT 256
#define NROWS 256      // B*S
#define BBS 128        // S
#define DD 128
#define FF 512
#define VV 1024
#define DK 32
#define LL 2

// ---------------- device scratch (no allocations allowed) ----------------
__device__ float g_x[NROWS*DD];
__device__ float g_qkv[NROWS*384];
__device__ float g_att[NROWS*DD];
__device__ float g_ff[NROWS*FF];
__device__ float g_ffp[4][NROWS*DD];
__device__ float g_twqkv[LL][DD*384];
__device__ float g_two[LL][DD*DD];
__device__ float g_tw1[LL][DD*FF];
__device__ float g_tw2[LL][FF*DD];
__device__ float g_twout[DD*VV];
__device__ unsigned g_count;
__device__ unsigned g_gen;

struct Params {
    const int* tokens; const float* emb; const float* pos;
    const float* Wq; const float* bq; const float* Wk; const float* bk;
    const float* Wv; const float* bv; const float* Wo; const float* bo;
    const float* W1; const float* b1; const float* W2; const float* b2;
    const float* g1; const float* be1; const float* g2; const float* be2;
    const float* Wout; const float* bout;
    float* out;
};

// ---------------- l_mul elementwise transform ----------------
// Reference: e = floor(log2|x|)+1; m = x*2^-e; r = round(m*8); term = f(x)*f(w)
// with f(x) = r * 2^(2e-3). (Validated: rel_err 6.5e-8 in prior rounds.)
__device__ __forceinline__ float lmul_f(float x) {
    float ax = fabsf(x);
    if (ax == 0.0f) return 0.0f;
    int e = (int)floorf(log2f(ax)) + 1;
    if (e < -60 || e > 60) {
        // out-of-fast-range: exact fallback
        float m = ldexpf(x, -e);
        float r = rintf(m * 8.0f);
        return ldexpf(r, 2*e - 3);
    }
    float m = x * __int_as_float((unsigned)(127 - e) << 23);    // exact 2^-e
    float r = rintf(m * 8.0f);                                   // half-to-even
    return r * __int_as_float((unsigned)((2*e - 3) + 127) << 23);// exact 2^(2e-3)
}

// ---------------- grid barrier (cg-style, generation counter) ----------------
__device__ __forceinline__ void gbar() {
    __syncthreads();
    if (threadIdx.x == 0) {
        __threadfence();
        unsigned gen = *((volatile unsigned*)&g_gen);
        if (atomicAdd(&g_count, 1u) == NB - 1u) {
            atomicExch(&g_count, 0u);
            __threadfence();
            atomicExch(&g_gen, gen + 1u);
        } else {
            while (*((volatile unsigned*)&g_gen) == gen) __nanosleep(32);
        }
        __threadfence();
    }
    __syncthreads();
}

// ---------------- phase 0: weight transform + embed ----------------
__device__ void transform_all(const Params& P) {
    const int t0 = blockIdx.x * NT + threadIdx.x;
    const int STEP = NB * NT;
    // qkv combined: tw[l][k*384+n]
    for (int i = t0; i < LL*DD*384; i += STEP) {
        int l = i / (DD*384); int r = i - l*(DD*384);
        int k = r / 384, n = r - k*384;
        const float* src; int nn;
        if (n < 128)      { src = P.Wq + l*DD*DD; nn = n; }
        else if (n < 256) { src = P.Wk + l*DD*DD; nn = n - 128; }
        else              { src = P.Wv + l*DD*DD; nn = n - 256; }
        g_twqkv[l][k*384 + n] = lmul_f(src[nn*DD + k]);
    }
    for (int i = t0; i < LL*DD*DD; i += STEP) {
        int l = i / (DD*DD); int r = i - l*(DD*DD);
        int k = r >> 7, n = r & 127;
        g_two[l][k*DD + n] = lmul_f(P.Wo[l*DD*DD + n*DD + k]);
    }
    for (int i = t0; i < LL*DD*FF; i += STEP) {
        int l = i / (DD*FF); int r = i - l*(DD*FF);
        int k = r >> 9, n = r & 511;  // k<128, n<512
        g_tw1[l][k*FF + n] = lmul_f(P.W1[l*FF*DD + n*DD + k]);
    }
    for (int i = t0; i < LL*FF*DD; i += STEP) {
        int l = i / (FF*DD); int r = i - l*(FF*DD);
        int k = r >> 7, n = r & 127;  // k<512, n<128
        g_tw2[l][k*DD + n] = lmul_f(P.W2[l*DD*FF + n*FF + k]);
    }
    for (int i = t0; i < DD*VV; i += STEP) {
        int k = i >> 10, n = i & 1023;
        g_twout[k*VV + n] = lmul_f(P.Wout[n*DD + k]);
    }
    // embedding + positional
    for (int i = t0; i < NROWS*DD; i += STEP) {
        int row = i >> 7, d = i & 127;
        int s = row & (BBS - 1);
        g_x[i] = P.emb[P.tokens[row]*DD + d] + P.pos[s*DD + d];
    }
}

// ---------------- GEMM tile: 8 rows x 128 cols, K-chunk = 128 ----------------
// Y[row0+r][col0+c] (+= handled via partial buffers) = sum_k f(X[.,kbeg+k]) * W[(kbeg+k)*N + col0+c] + bias[c]
__device__ __forceinline__ void gemm_tile(
    const float* __restrict__ X, int ldx, int kbeg,
    const float* __restrict__ W, int N,
    const float* __restrict__ bias,    // indexed [c]; may be null
    bool relu,
    float* __restrict__ Y, int ldy,
    int row0, int col0, float* __restrict__ xs /* 8*132 */)
{
    const int tid = threadIdx.x;
    #pragma unroll
    for (int i = 0; i < 4; ++i) {
        int idx = tid + i*NT;              // 0..1023
        int r = idx >> 7, k = idx & 127;
        xs[r*132 + k] = lmul_f(X[(row0 + r)*ldx + kbeg + k]);
    }
    __syncthreads();
    const int c = tid & 127;
    const int rg = (tid >> 7) << 2;        // 0 or 4
    const float* wp = W + (size_t)kbeg * N + col0 + c;
    const float* x0p = xs + (rg+0)*132;
    const float* x1p = xs + (rg+1)*132;
    const float* x2p = xs + (rg+2)*132;
    const float* x3p = xs + (rg+3)*132;
    float a0 = 0.f, a1 = 0.f, a2 = 0.f, a3 = 0.f;
    #pragma unroll 8
    for (int k = 0; k < 128; k += 4) {
        float4 v0 = *(const float4*)(x0p + k);
        float4 v1 = *(const float4*)(x1p + k);
        float4 v2 = *(const float4*)(x2p + k);
        float4 v3 = *(const float4*)(x3p + k);
        float w0 = wp[(size_t)(k+0)*N];
        float w1 = wp[(size_t)(k+1)*N];
        float w2 = wp[(size_t)(k+2)*N];
        float w3 = wp[(size_t)(k+3)*N];
        a0 = fmaf(v0.x, w0, a0); a1 = fmaf(v1.x, w0, a1); a2 = fmaf(v2.x, w0, a2); a3 = fmaf(v3.x, w0, a3);
        a0 = fmaf(v0.y, w1, a0); a1 = fmaf(v1.y, w1, a1); a2 = fmaf(v2.y, w1, a2); a3 = fmaf(v3.y, w1, a3);
        a0 = fmaf(v0.z, w2, a0); a1 = fmaf(v1.z, w2, a1); a2 = fmaf(v2.z, w2, a2); a3 = fmaf(v3.z, w2, a3);
        a0 = fmaf(v0.w, w3, a0); a1 = fmaf(v1.w, w3, a1); a2 = fmaf(v2.w, w3, a2); a3 = fmaf(v3.w, w3, a3);
    }
    float b = bias ? bias[c] : 0.f;
    a0 += b; a1 += b; a2 += b; a3 += b;
    if (relu) {
        a0 = fmaxf(a0, 0.f); a1 = fmaxf(a1, 0.f);
        a2 = fmaxf(a2, 0.f); a3 = fmaxf(a3, 0.f);
    }
    Y[(size_t)(row0+rg+0)*ldy + col0 + c] = a0;
    Y[(size_t)(row0+rg+1)*ldy + col0 + c] = a1;
    Y[(size_t)(row0+rg+2)*ldy + col0 + c] = a2;
    Y[(size_t)(row0+rg+3)*ldy + col0 + c] = a3;
    __syncthreads();
}

// ---------------- attention tile: (b, h, 8-query block); warp per query -------
__device__ __forceinline__ void attn_tile(
    const float* __restrict__ qkv, float* __restrict__ attout,
    int b, int h, int qb, float* __restrict__ sm)
{
    float* ksh = sm;               // 128*33
    float* vsh = sm + 4224;        // 128*33
    float* qsh = sm + 8448;        // 8*32
    float* psh = sm + 8704;        // 8*128
    const int tid = threadIdx.x;
    #pragma unroll
    for (int i = 0; i < 16; ++i) {
        int idx = tid + i*NT;       // 0..4095
        int j = idx >> 5, d = idx & 31;
        const float* base = qkv + (size_t)(b*BBS + j)*384 + h*DK + d;
        ksh[j*33 + d] = base[128];
        vsh[j*33 + d] = base[256];
    }
    {
        int qi = tid >> 5, d = tid & 31;   // 8*32 = 256 = NT
        qsh[tid] = qkv[(size_t)(b*BBS + qb*8 + qi)*384 + h*DK + d];
    }
    __syncthreads();
    const int wid = tid >> 5, lane = tid & 31;
    const int q = qb*8 + wid;
    float qr[32];
    #pragma unroll
    for (int d = 0; d < 32; d += 4) {
        float4 t = *(const float4*)(qsh + wid*32 + d);
        qr[d] = t.x; qr[d+1] = t.y; qr[d+2] = t.z; qr[d+3] = t.w;
    }
    const float* k0 = ksh + (lane     )*33;
    const float* k1 = ksh + (lane + 32)*33;
    const float* k2 = ksh + (lane + 64)*33;
    const float* k3 = ksh + (lane + 96)*33;
    float s0 = 0.f, s1 = 0.f, s2 = 0.f, s3 = 0.f;
    #pragma unroll
    for (int d = 0; d < 32; ++d) {
        float qd = qr[d];
        s0 = fmaf(qd, k0[d], s0);
        s1 = fmaf(qd, k1[d], s1);
        s2 = fmaf(qd, k2[d], s2);
        s3 = fmaf(qd, k3[d], s3);
    }
    const float scale = 0.17677669529663687f;  // 1/sqrt(32)
    s0 *= scale; s1 *= scale; s2 *= scale; s3 *= scale;
    float m = fmaxf(fmaxf(s0, s1), fmaxf(s2, s3));
    #pragma unroll
    for (int o = 16; o; o >>= 1) m = fmaxf(m, __shfl_xor_sync(0xffffffffu, m, o));
    float p0 = expf(s0 - m), p1 = expf(s1 - m), p2 = expf(s2 - m), p3 = expf(s3 - m);
    float lsum = p0 + p1 + p2 + p3;
    #pragma unroll
    for (int o = 16; o; o >>= 1) lsum += __shfl_xor_sync(0xffffffffu, lsum, o);
    float* pp = psh + wid*128;
    pp[lane     ] = p0;
    pp[lane + 32] = p1;
    pp[lane + 64] = p2;
    pp[lane + 96] = p3;
    __syncwarp();
    float o0 = 0.f, o1 = 0.f, o2 = 0.f, o3 = 0.f;
    #pragma unroll 8
    for (int j = 0; j < 128; j += 4) {
        o0 = fmaf(pp[j+0], vsh[(j+0)*33 + lane], o0);
        o1 = fmaf(pp[j+1], vsh[(j+1)*33 + lane], o1);
        o2 = fmaf(pp[j+2], vsh[(j+2)*33 + lane], o2);
        o3 = fmaf(pp[j+3], vsh[(j+3)*33 + lane], o3);
    }
    attout[(size_t)(b*BBS + q)*DD + h*DK + lane] = ((o0 + o1) + (o2 + o3)) / lsum;
    __syncthreads();
}

// ---------------- O-proj + residual + LN1 (tile = 4 rows, full 128 cols) ------
__device__ __forceinline__ void oproj_ln(
    const float* __restrict__ att, const float* __restrict__ W,
    const float* __restrict__ bo, const float* __restrict__ g1,
    const float* __restrict__ be1, float* __restrict__ x,
    float* __restrict__ sm)
{
    if (blockIdx.x >= 64) return;
    const int row0 = blockIdx.x * 4;
    float* as   = sm;          // 4*132
    float* vals = sm + 544;    // 4*132
    float* st   = sm + 1088;   // 8
    const int tid = threadIdx.x;
    #pragma unroll
    for (int i = 0; i < 2; ++i) {
        int idx = tid + i*NT;          // 0..511
        int r = idx >> 7, k = idx & 127;
        as[r*132 + k] = lmul_f(att[(row0 + r)*DD + k]);
    }
    __syncthreads();
    const int c = tid & 127, rg = tid >> 7;       // rows rg*2, rg*2+1
    const float* x0p = as + (rg*2    )*132;
    const float* x1p = as + (rg*2 + 1)*132;
    const float* wp = W + c;
    float a0 = 0.f, a1 = 0.f;
    #pragma unroll 8
    for (int k = 0; k < 128; k += 4) {
        float4 v0 = *(const float4*)(x0p + k);
        float4 v1 = *(const float4*)(x1p + k);
        float w0 = wp[(k+0)*DD], w1 = wp[(k+1)*DD], w2 = wp[(k+2)*DD], w3 = wp[(k+3)*DD];
        a0 = fmaf(v0.x, w0, a0); a1 = fmaf(v1.x, w0, a1);
        a0 = fmaf(v0.y, w1, a0); a1 = fmaf(v1.y, w1, a1);
        a0 = fmaf(v0.z, w2, a0); a1 = fmaf(v1.z, w2, a1);
        a0 = fmaf(v0.w, w3, a0); a1 = fmaf(v1.w, w3, a1);
    }
    float b = bo[c];
    const int r0 = row0 + rg*2, r1 = r0 + 1;
    float v0 = x[r0*DD + c] + a0 + b;
    float v1 = x[r1*DD + c] + a1 + b;
    vals[(rg*2    )*132 + c] = v0;
    vals[(rg*2 + 1)*132 + c] = v1;
    __syncthreads();
    const int wid = tid >> 5, lane = tid & 31;
    if (wid < 4) {
        float s = 0.f, sq = 0.f;
        #pragma unroll
        for (int i = 0; i < 4; ++i) {
            float v = vals[wid*132 + lane + i*32];
            s += v; sq = fmaf(v, v, sq);
        }
        #pragma unroll
        for (int o = 16; o; o >>= 1) {
            s  += __shfl_xor_sync(0xffffffffu, s, o);
            sq += __shfl_xor_sync(0xffffffffu, sq, o);
        }
        if (lane == 0) {
            float mean = s * (1.f/128.f);
            float var  = sq * (1.f/128.f) - mean*mean;
            st[wid*2]     = mean;
            st[wid*2 + 1] = rsqrtf(var + 1e-5f);
        }
    }
    __syncthreads();
    {
        float gm = g1[c], bb = be1[c];
        float m0 = st[(rg*2)*2],     rs0 = st[(rg*2)*2 + 1];
        float m1 = st[(rg*2+1)*2],   rs1 = st[(rg*2+1)*2 + 1];
        x[r0*DD + c] = (v0 - m0)*rs0*gm + bb;
        x[r1*DD + c] = (v1 - m1)*rs1*gm + bb;
    }
    __syncthreads();
}

// ---------------- FF2 partial combine + bias + residual + LN2 -----------------
__device__ __forceinline__ void ff2_ln(
    const float* __restrict__ b2, const float* __restrict__ g2,
    const float* __restrict__ be2, float* __restrict__ x,
    float* __restrict__ sm)
{
    float* vals = sm;         // 2*132
    float* st   = sm + 272;   // 4
    const int tid = threadIdx.x;
    const int c = tid & 127, rg = tid >> 7;
    const int row = blockIdx.x*2 + rg;
    float v = x[row*DD + c] + b2[c];
    #pragma unroll
    for (int ks = 0; ks < 4; ++ks) v += g_ffp[ks][row*DD + c];
    vals[rg*132 + c] = v;
    __syncthreads();
    const int wid = tid >> 5, lane = tid & 31;
    if (wid < 2) {
        float s = 0.f, sq = 0.f;
        #pragma unroll
        for (int i = 0; i < 4; ++i) {
            float t = vals[wid*132 + lane + i*32];
            s += t; sq = fmaf(t, t, sq);
        }
        #pragma unroll
        for (int o = 16; o; o >>= 1) {
            s  += __shfl_xor_sync(0xffffffffu, s, o);
            sq += __shfl_xor_sync(0xffffffffu, sq, o);
        }
        if (lane == 0) {
            float mean = s * (1.f/128.f);
            float var  = sq * (1.f/128.f) - mean*mean;
            st[wid*2]     = mean;
            st[wid*2 + 1] = rsqrtf(var + 1e-5f);
        }
    }
    __syncthreads();
    x[row*DD + c] = (v - st[rg*2])*st[rg*2 + 1]*g2[c] + be2[c];
    __syncthreads();
}

// ---------------- the one persistent kernel ----------------
__global__ void __launch_bounds__(NT, 1) model_kernel(Params P) {
    __shared__ __align__(16) float sm[9760];

    // P0: weight transforms + embedding
    transform_all(P);
    gbar();

    for (int l = 0; l < LL; ++l) {
        // P1: QKV fused GEMM — 96 tiles (32 row-tiles x 3 col-tiles)
        if (blockIdx.x < 96) {
            int rt = blockIdx.x & 31, ct = blockIdx.x >> 5;
            const float* segb = (ct == 0 ? P.bq : ct == 1 ? P.bk : P.bv) + l*DD;
            gemm_tile(g_x, DD, 0, g_twqkv[l], 384, segb, false,
                      g_qkv, 384, rt*8, ct*128, sm);
        }
        gbar();

        // P2: attention — 128 tiles (b, h, qb)
        {
            int vt = blockIdx.x;
            int b = vt >> 6, h = (vt >> 4) & 3, qb = vt & 15;
            attn_tile(g_qkv, g_att, b, h, qb, sm);
        }
        gbar();

        // P3: O-proj + residual + LN1 — 64 tiles
        oproj_ln(g_att, g_two[l], P.bo + l*DD, P.g1 + l*DD, P.be1 + l*DD, g_x, sm);
        gbar();

        // P4: FF1 + relu — 128 tiles
        {
            int rt = blockIdx.x & 31, ct = blockIdx.x >> 5;
            gemm_tile(g_x, DD, 0, g_tw1[l], FF, P.b1 + l*FF + ct*128, true,
                      g_ff, FF, rt*8, ct*128, sm);
        }
        gbar();

        // P5: FF2 k-split partials — 128 tiles (32 row-tiles x 4 k-chunks)
        {
            int rt = blockIdx.x & 31, ks = blockIdx.x >> 5;
            gemm_tile(g_ff, FF, ks*128, g_tw2[l], DD, (const float*)0, false,
                      g_ffp[ks], DD, rt*8, 0, sm);
        }
        gbar();

        // P6: partial sum + bias + residual + LN2
        ff2_ln(P.b2 + l*DD, P.g2 + l*DD, P.be2 + l*DD, g_x, sm);
        gbar();
    }

    // P7: final vocab projection — 256 tiles, 2 per block
    #pragma unroll
    for (int t = 0; t < 2; ++t) {
        int vt = blockIdx.x + t*NB;
        int rt = vt & 31, ct = vt >> 5;
        gemm_tile(g_x, DD, 0, g_twout, VV, P.bout + ct*128, false,
                  P.out, VV, rt*8, ct*128, sm);
    }
}

extern "C" void kernel_launch(void* const* d_in, const int* in_sizes, int n_in,
                              void* d_out, int out_size) {
    Params P;
    P.tokens = (const int*)  d_in[0];
    P.emb    = (const float*)d_in[1];
    P.pos    = (const float*)d_in[2];
    P.Wq     = (const float*)d_in[3];
    P.bq     = (const float*)d_in[4];
    P.Wk     = (const float*)d_in[5];
    P.bk     = (const float*)d_in[6];
    P.Wv     = (const float*)d_in[7];
    P.bv     = (const float*)d_in[8];
    P.Wo     = (const float*)d_in[9];
    P.bo     = (const float*)d_in[10];
    P.W1     = (const float*)d_in[11];
    P.b1     = (const float*)d_in[12];
    P.W2     = (const float*)d_in[13];
    P.b2     = (const float*)d_in[14];
    P.g1     = (const float*)d_in[15];
    P.be1    = (const float*)d_in[16];
    P.g2     = (const float*)d_in[17];
    P.be2    = (const float*)d_in[18];
    P.Wout   = (const float*)d_in[19];
    P.bout   = (const float*)d_in[20];
    P.out    = (float*)d_out;

    model_kernel<<<NB, NT>>>(P);
}